// round 15
// baseline (speedup 1.0000x reference)
#include <cuda_runtime.h>
#include <cuda_fp16.h>
#include <cstdint>

#define BATCH 4
#define SEQ   2048
#define DIM   1024

typedef __half f16;

static const long NX = (long)BATCH * SEQ * DIM;   // 8388608
static const long NW = (long)DIM * DIM;           // 1048576
#define DNX ((long)BATCH * SEQ * DIM)

// ---------------- scratch (device globals; allocation-free) ----------------
__device__ __align__(128) f16   g_xh[(long)BATCH*SEQ*DIM];
// [0]=Wq^T, [1]=Wk^T, [2]=Wv (hi only for Wv)
__device__ __align__(128) f16   g_wh[3][(long)DIM*DIM];
__device__ __align__(128) f16   g_wl[2][(long)DIM*DIM];
// M' split-K fp32 partials and final f16 hi
__device__ __align__(128) float g_mpart[4*(long)DIM*DIM];
__device__ __align__(128) f16   g_mh[(long)DIM*DIM];
// stacked outputs: [0]=T (hi), [1]=V^T (hi, [b][e][s])
__device__ __align__(128) f16   g_oh[2*(long)BATCH*SEQ*DIM];
// logits then probs (in-place softmax)
__device__ __align__(128) f16   g_ph[(long)BATCH*SEQ*SEQ];

// ---------------- PTX helpers (arch-generic; NO tcgen05) ----------------
__device__ __forceinline__ uint32_t smem_u32(const void* p) {
    uint32_t a;
    asm("{ .reg .u64 t; cvta.to.shared.u64 t, %1; cvt.u32.u64 %0, t; }" : "=r"(a) : "l"(p));
    return a;
}
__device__ __forceinline__ void cp16(uint32_t saddr, const void* g) {
    asm volatile("cp.async.cg.shared.global [%0], [%1], 16;" :: "r"(saddr), "l"(g) : "memory");
}
#define CP_COMMIT() asm volatile("cp.async.commit_group;" ::: "memory")

__device__ __forceinline__ void ldsm_x4(uint32_t* r, uint32_t addr) {
    asm volatile("ldmatrix.sync.aligned.m8n8.x4.shared.b16 {%0,%1,%2,%3}, [%4];"
        : "=r"(r[0]), "=r"(r[1]), "=r"(r[2]), "=r"(r[3]) : "r"(addr));
}
__device__ __forceinline__ void mma16816(float* c, const uint32_t* a, const uint32_t* b) {
    asm volatile("mma.sync.aligned.m16n8k16.row.col.f32.f16.f16.f32 "
        "{%0,%1,%2,%3}, {%4,%5,%6,%7}, {%8,%9}, {%0,%1,%2,%3};"
        : "+f"(c[0]), "+f"(c[1]), "+f"(c[2]), "+f"(c[3])
        : "r"(a[0]), "r"(a[1]), "r"(a[2]), "r"(a[3]), "r"(b[0]), "r"(b[1]));
}

__device__ __forceinline__ uint32_t swz(int row, int kc) {
    return (uint32_t)(row * 64 + ((kc ^ ((row >> 1) & 3)) << 4));
}

__device__ __forceinline__ void fsplit(float f, f16& h, f16& l) {
    h = __float2half_rn(f);
    l = __float2half_rn(f - __half2float(h));
}

// ---------------- SMEM layout ----------------
#define STAGES 3
#define STAGE_BYTES 32768
#define EPI_LD 132
#define SMEM_TOTAL (STAGES * STAGE_BYTES)

// =====================================================================
// fp16 hi/lo NT GEMM via mma.sync: 128x128 CTA tile, 128 threads,
// 4 warps x (64x64) warp tile.
// npass=3: hh + hl + lh ; npass=2: hh + lh ; npass=1: hh only
// mode 0: fp32 C
// mode 1: f16 C (hi; lo iff Clo != nullptr)
// mode 2: f16 C transposed (hi; lo iff Clo)
// mode 5: f16 C, scaled by 1/32, hi only  (scores -> logits)
// mode 6: fused (operands from device globals):
//         bz==0   -> V^T = X_hi @ Wv_hi^T (1-pass, mode-2 hi into g_oh+DNX)
//         bz=1..4 -> M' split-K slice bz-1 (2-pass, fp32 into g_mpart)
// =====================================================================
__global__ void __launch_bounds__(128, 2) gemm_f16x(
    const f16* __restrict__ Ahi, const f16* __restrict__ Alo,
    const f16* __restrict__ Bhi, const f16* __restrict__ Blo,
    float* __restrict__ Cf, f16* __restrict__ Chi, f16* __restrict__ Clo,
    int K, int ldA, int ldB, int ldC,
    long strideA, long strideB, long strideC,
    int causal, int kclamp, int mode, int npass)
{
    const int bx = blockIdx.x, bz = blockIdx.z;
    // heavy-tile-first dispatch when k-clamped
    const int by = kclamp ? ((int)gridDim.y - 1 - (int)blockIdx.y) : (int)blockIdx.y;
    if (causal && bx > by) return;

    // ---- resolve operands / submode ----
    const f16 *Ah = Ahi, *Al = Alo, *Bh = Bhi, *Bl = Blo;
    float* cf = Cf; f16 *chi = Chi, *clo = Clo;
    int emode = mode, ldc = ldC, np = npass, lda = ldA, ldb = ldB;
    long sA = strideA, sB = strideB, sC = strideC;
    int kk = K, kbase = 0, zi = bz;

    if (mode == 6) {
        if (bz == 0) {
            // V^T projection (1-pass, hi only)
            Ah = g_xh; Al = nullptr; Bh = g_wh[2]; Bl = nullptr;
            np = 1; emode = 2; ldc = SEQ; sC = (long)DIM * SEQ;
            chi = g_oh + DNX; clo = nullptr;
            lda = DIM; ldb = DIM; sA = 0; sB = 0; kk = DIM; zi = 0;
        } else {
            if (by >= DIM / 128) return;
            int zz = bz - 1;
            // M' slice: A = Wk^T (hi+lo), B = Wq^T (hi only) -> 2-pass
            Ah = g_wh[1]; Al = g_wl[1]; Bh = g_wh[0]; Bl = nullptr;
            np = 2; emode = 0; cf = g_mpart + (long)zz * NW;
            ldc = DIM; sC = 0; lda = DIM; ldb = DIM; sA = 0; sB = 0;
            kk = DIM / 4; kbase = zz * (DIM / 4); zi = 0;
        }
    }

    extern __shared__ char smem[];
    const uint32_t sbase = smem_u32(smem);
    const int tid  = threadIdx.x;        // 0..127
    const int lane = tid & 31;
    const int wid  = tid >> 5;           // 0..3
    const int wm   = wid >> 1;           // 0..1 : 64 rows
    const int wn   = wid & 1;            // 0..1 : 64 cols

    const int kmax    = kclamp ? min(kk, (by + 1) * 128) : kk;
    const int nchunks = kmax >> 5;       // BK = 32

    const f16* pAh = Ah + zi * sA + (long)by * 128 * lda;
    const f16* pAl = Al ? (Al + zi * sA + (long)by * 128 * lda) : nullptr;
    const f16* pBh = Bh + zi * sB + (long)bx * 128 * ldb;
    const f16* pBl = Bl ? (Bl + zi * sB + (long)bx * 128 * ldb) : nullptr;

    auto load_chunk = [&](int c) {
        const uint32_t st = sbase + (uint32_t)(c % STAGES) * STAGE_BYTES;
        const int k0 = kbase + (c << 5);
        #pragma unroll
        for (int i = 0; i < 4; i++) {
            int id  = tid + i * 128;       // 0..511
            int row = id >> 2, kc = id & 3;
            uint32_t so = swz(row, kc);
            long gA = (long)row * lda + k0 + kc * 8;
            long gB = (long)row * ldb + k0 + kc * 8;
            cp16(st +         so, pAh + gA);
            if (np >= 2) cp16(st +  8192 + so, pAl + gA);
            cp16(st + 16384 + so, pBh + gB);
            if (np == 3)  cp16(st + 24576 + so, pBl + gB);
        }
        CP_COMMIT();
    };

    float acc[4][8][4];
    #pragma unroll
    for (int i = 0; i < 4; i++)
        #pragma unroll
        for (int j = 0; j < 8; j++)
            #pragma unroll
            for (int p = 0; p < 4; p++) acc[i][j][p] = 0.f;

    load_chunk(0);
    if (nchunks > 1) load_chunk(1);

    const int lrow = lane & 15;
    const int lsel = lane >> 4;
    const int arow = wm * 64 + lrow;
    const int brow = wn * 64 + lrow;

    for (int c = 0; c < nchunks; c++) {
        if (c + 1 < nchunks) asm volatile("cp.async.wait_group 1;" ::: "memory");
        else                 asm volatile("cp.async.wait_group 0;" ::: "memory");
        __syncthreads();

        if (c + 2 < nchunks) load_chunk(c + 2);

        const uint32_t st  = sbase + (uint32_t)(c % STAGES) * STAGE_BYTES;
        const uint32_t sAh = st, sAl = st + 8192, sBh = st + 16384, sBl = st + 24576;

        #pragma unroll
        for (int ks = 0; ks < 2; ks++) {
            const int kc = ks * 2 + lsel;
            uint32_t bh[8][2];
            #pragma unroll
            for (int nq = 0; nq < 4; nq++) {
                int r = brow + nq * 16;
                uint32_t t4[4];
                ldsm_x4(t4, sBh + swz(r, kc));
                bh[nq*2][0] = t4[0]; bh[nq*2][1] = t4[2];
                bh[nq*2+1][0] = t4[1]; bh[nq*2+1][1] = t4[3];
            }
            uint32_t aH[4][4];
            #pragma unroll
            for (int mt = 0; mt < 4; mt++)
                ldsm_x4(aH[mt], sAh + swz(arow + mt * 16, kc));

            // pass 1: aH x bh
            #pragma unroll
            for (int mt = 0; mt < 4; mt++)
                #pragma unroll
                for (int nt = 0; nt < 8; nt++)
                    mma16816(acc[mt][nt], aH[mt], bh[nt]);

            // pass 2 (np==3): aH x bl
            if (np == 3) {
                uint32_t bl[8][2];
                #pragma unroll
                for (int nq = 0; nq < 4; nq++) {
                    int r = brow + nq * 16;
                    uint32_t t4[4];
                    ldsm_x4(t4, sBl + swz(r, kc));
                    bl[nq*2][0] = t4[0]; bl[nq*2][1] = t4[2];
                    bl[nq*2+1][0] = t4[1]; bl[nq*2+1][1] = t4[3];
                }
                #pragma unroll
                for (int mt = 0; mt < 4; mt++)
                    #pragma unroll
                    for (int nt = 0; nt < 8; nt++)
                        mma16816(acc[mt][nt], aH[mt], bl[nt]);
            }

            // pass 3 (np>=2): aL x bh (aL streamed)
            if (np >= 2) {
                uint32_t aL[2][4];
                ldsm_x4(aL[0], sAl + swz(arow, kc));
                #pragma unroll
                for (int mt = 0; mt < 4; mt++) {
                    const int cur = mt & 1;
                    if (mt < 3)
                        ldsm_x4(aL[cur ^ 1], sAl + swz(arow + (mt + 1) * 16, kc));
                    #pragma unroll
                    for (int nt = 0; nt < 8; nt++)
                        mma16816(acc[mt][nt], aL[cur], bh[nt]);
                }
            }
        }
    }

    // ---- epilogue: stage fp32 tile in smem, then coalesced global writes ----
    __syncthreads();
    float* buf = (float*)smem;
    {
        const int rq = lane >> 2;
        const int cq = (lane & 3) * 2;
        #pragma unroll
        for (int mt = 0; mt < 4; mt++)
            #pragma unroll
            for (int nt = 0; nt < 8; nt++) {
                int r0 = wm * 64 + mt * 16 + rq;
                int c0 = wn * 64 + nt * 8 + cq;
                *(float2*)&buf[r0 * EPI_LD + c0]       = make_float2(acc[mt][nt][0], acc[mt][nt][1]);
                *(float2*)&buf[(r0 + 8) * EPI_LD + c0] = make_float2(acc[mt][nt][2], acc[mt][nt][3]);
            }
    }
    __syncthreads();

    if (emode == 0) {
        int r = tid;
        long row = (long)by * 128 + r;
        float4* dst = (float4*)(cf + zi * sC + row * ldc + (long)bx * 128);
        #pragma unroll
        for (int i = 0; i < 32; i++)
            dst[i] = *(float4*)&buf[r * EPI_LD + i * 4];
    } else if (emode == 1) {
        int r = tid;
        long row = (long)by * 128 + r;
        f16* dh = chi + zi * sC + row * ldc + (long)bx * 128;
        f16* dl = clo ? (clo + zi * sC + row * ldc + (long)bx * 128) : nullptr;
        #pragma unroll
        for (int v = 0; v < 16; v++) {
            uint4 uh, ul;
            uint32_t* phh = (uint32_t*)&uh; uint32_t* pll = (uint32_t*)&ul;
            #pragma unroll
            for (int p = 0; p < 4; p++) {
                float f0 = buf[r * EPI_LD + v * 8 + p * 2];
                float f1 = buf[r * EPI_LD + v * 8 + p * 2 + 1];
                f16 h0, l0, h1, l1;
                fsplit(f0, h0, l0); fsplit(f1, h1, l1);
                phh[p] = (uint32_t)*(uint16_t*)&h0 | ((uint32_t)*(uint16_t*)&h1 << 16);
                pll[p] = (uint32_t)*(uint16_t*)&l0 | ((uint32_t)*(uint16_t*)&l1 << 16);
            }
            *(uint4*)(dh + v * 8) = uh;
            if (dl) *(uint4*)(dl + v * 8) = ul;
        }
    } else if (emode == 5) {
        // scaled f16 logits, hi only
        int r = tid;
        long row = (long)by * 128 + r;
        f16* dh = chi + zi * sC + row * ldc + (long)bx * 128;
        #pragma unroll
        for (int v = 0; v < 16; v++) {
            uint4 uh; uint32_t* phh = (uint32_t*)&uh;
            #pragma unroll
            for (int p = 0; p < 4; p++) {
                f16 h0 = __float2half_rn(buf[r * EPI_LD + v * 8 + p * 2]     * 0.03125f);
                f16 h1 = __float2half_rn(buf[r * EPI_LD + v * 8 + p * 2 + 1] * 0.03125f);
                phh[p] = (uint32_t)*(uint16_t*)&h0 | ((uint32_t)*(uint16_t*)&h1 << 16);
            }
            *(uint4*)(dh + v * 8) = uh;
        }
    } else {
        // emode 2: transposed out: Ct[e][s_local], batch derived from global row
        int cc = tid;
        int rowbase = by * 128;
        int b = rowbase / SEQ;
        int sloc = rowbase % SEQ;
        long e = (long)bx * 128 + cc;
        f16* dh = chi + b * sC + e * ldc + sloc;
        #pragma unroll
        for (int v = 0; v < 16; v++) {
            uint4 uh;
            uint32_t* phh = (uint32_t*)&uh;
            #pragma unroll
            for (int p = 0; p < 4; p++) {
                f16 h0 = __float2half_rn(buf[(v * 8 + p * 2)     * EPI_LD + cc]);
                f16 h1 = __float2half_rn(buf[(v * 8 + p * 2 + 1) * EPI_LD + cc]);
                phh[p] = (uint32_t)*(uint16_t*)&h0 | ((uint32_t)*(uint16_t*)&h1 << 16);
            }
            *(uint4*)(dh + v * 8) = uh;
        }
    }
}

// ---------------- fp32 -> f16 hi-only split (X and Wv in one launch) ----------------
__global__ void __launch_bounds__(256) split_all(
    const float* __restrict__ X, const float* __restrict__ Wv,
    f16* __restrict__ xh, f16* __restrict__ wvh)
{
    const float* src = (blockIdx.y == 0) ? X : Wv;
    f16* dst = (blockIdx.y == 0) ? xh : wvh;
    long n = (blockIdx.y == 0) ? NX : NW;
    long i = ((long)blockIdx.x * 256 + threadIdx.x) * 4;
    if (i >= n) return;
    float4 v = *(const float4*)(src + i);
    float f[4] = {v.x, v.y, v.z, v.w};
    uint32_t h2[2];
    #pragma unroll
    for (int p = 0; p < 2; p++) {
        f16 h0 = __float2half_rn(f[p*2]);
        f16 h1 = __float2half_rn(f[p*2+1]);
        h2[p] = (uint32_t)*(uint16_t*)&h0 | ((uint32_t)*(uint16_t*)&h1 << 16);
    }
    *(uint2*)(dst + i) = make_uint2(h2[0], h2[1]);
}

// transpose + split for Wq (z=0) and Wk (z=1): out[d][e] = in[e][d]
__global__ void __launch_bounds__(256) tsplit_w(
    const float* __restrict__ w0, const float* __restrict__ w1,
    f16* __restrict__ hi, f16* __restrict__ lo)
{
    const float* src = (blockIdx.z == 0) ? w0 : w1;
    f16* dh = hi + (long)blockIdx.z * NW;
    f16* dl = lo + (long)blockIdx.z * NW;

    __shared__ float t[32][33];
    const int tx = threadIdx.x & 31;
    const int ty = threadIdx.x >> 5;   // 0..7
    int x = blockIdx.x * 32 + tx;
    #pragma unroll
    for (int j = 0; j < 4; j++) {
        int y = blockIdx.y * 32 + ty + j * 8;
        t[ty + j * 8][tx] = src[(long)y * DIM + x];
    }
    __syncthreads();
    int xo = blockIdx.y * 32 + tx;
    #pragma unroll
    for (int j = 0; j < 4; j++) {
        int yo = blockIdx.x * 32 + ty + j * 8;
        float f = t[tx][ty + j * 8];
        f16 h, l;
        fsplit(f, h, l);
        dh[(long)yo * DIM + xo] = h;
        dl[(long)yo * DIM + xo] = l;
    }
}

// reduce 4 fp32 partials -> f16 hi only
__global__ void __launch_bounds__(256) reduce4_hi(
    const float* __restrict__ part, f16* __restrict__ hi)
{
    long i = ((long)blockIdx.x * 256 + threadIdx.x) * 4;
    if (i >= NW) return;
    float4 s = *(const float4*)(part + i);
    #pragma unroll
    for (int j = 1; j < 4; j++) {
        float4 v = *(const float4*)(part + j * NW + i);
        s.x += v.x; s.y += v.y; s.z += v.z; s.w += v.w;
    }
    float f[4] = {s.x, s.y, s.z, s.w};
    uint32_t h2[2];
    #pragma unroll
    for (int p = 0; p < 2; p++) {
        f16 h0 = __float2half_rn(f[p*2]);
        f16 h1 = __float2half_rn(f[p*2+1]);
        h2[p] = (uint32_t)*(uint16_t*)&h0 | ((uint32_t)*(uint16_t*)&h1 << 16);
    }
    *(uint2*)(hi + i) = make_uint2(h2[0], h2[1]);
}

// ---------------- causal softmax IN PLACE on f16 logits (vectorized) -------
// Reads/writes uint4 (8 halves). Masked lanes use -inf -> exp()=0, so the
// reductions are unchanged. Zero-fill only to end of the row's 128-block.
__global__ void __launch_bounds__(256) softmax_causal(f16* __restrict__ P)
{
    const long r = blockIdx.x;
    const int  q = (int)(r & (SEQ - 1));
    f16* row = P + r * SEQ;

    __shared__ float bufr[SEQ];
    __shared__ float red[256];

    const int tid  = threadIdx.x;
    const int len  = q + 1;
    const int zend = ((q >> 7) + 1) << 7;     // round up to 128
    const int nvec = (len + 7) >> 3;          // 8-half vectors covering [0,len)

    float m = -1e30f;
    for (int v = tid; v < nvec; v += 256) {
        uint4 u = *(const uint4*)(row + v * 8);
        const f16* h = (const f16*)&u;
        #pragma unroll
        for (int j = 0; j < 8; j++) {
            int idx = v * 8 + j;
            float f = (idx < len) ? __half2float(h[j]) : -1e30f;
            bufr[idx] = f;
            m = fmaxf(m, f);
        }
    }
    red[tid] = m;
    __syncthreads();
    #pragma unroll
    for (int s = 128; s > 0; s >>= 1) {
        if (tid < s) red[tid] = fmaxf(red[tid], red[tid + s]);
        __syncthreads();
    }
    m = red[0];
    __syncthreads();

    float sum = 0.f;
    for (int v = tid; v < nvec; v += 256) {
        #pragma unroll
        for (int j = 0; j < 8; j++) {
            int idx = v * 8 + j;
            float e = __expf(bufr[idx] - m);   // masked -> exp(-inf)=0
            bufr[idx] = e;
            sum += e;
        }
    }
    red[tid] = sum;
    __syncthreads();
    #pragma unroll
    for (int s = 128; s > 0; s >>= 1) {
        if (tid < s) red[tid] += red[tid + s];
        __syncthreads();
    }
    const float inv = 1.0f / red[0];
    __syncthreads();

    const int zvec = zend >> 3;
    for (int v = tid; v < zvec; v += 256) {
        uint4 u; f16* h = (f16*)&u;
        #pragma unroll
        for (int j = 0; j < 8; j++) {
            int idx = v * 8 + j;
            h[j] = (idx < len) ? __float2half_rn(bufr[idx] * inv) : __float2half(0.f);
        }
        *(uint4*)(row + v * 8) = u;
    }
}

// ---------------------------------------------------------------------------
extern "C" void kernel_launch(void* const* d_in, const int* in_sizes, int n_in,
                              void* d_out, int out_size)
{
    const float* X  = (const float*)d_in[0];
    const float* Wq = (const float*)d_in[1];
    const float* Wk = (const float*)d_in[2];
    const float* Wv = (const float*)d_in[3];
    float* out = (float*)d_out;

    f16 *xh, *wh, *wl, *mh, *oh, *ph;
    float *mpart;
    cudaGetSymbolAddress((void**)&xh, g_xh);
    cudaGetSymbolAddress((void**)&wh, g_wh);  cudaGetSymbolAddress((void**)&wl, g_wl);
    cudaGetSymbolAddress((void**)&mh, g_mh);
    cudaGetSymbolAddress((void**)&mpart, g_mpart);
    cudaGetSymbolAddress((void**)&oh, g_oh);
    cudaGetSymbolAddress((void**)&ph, g_ph);

    cudaFuncSetAttribute(gemm_f16x, cudaFuncAttributeMaxDynamicSharedMemorySize, SMEM_TOTAL);

    const long nX = NX, nW = NW;
    const int M = BATCH * SEQ;  // 8192

    dim3 thr256(256);
    dim3 thr128(128);

    // splits: X + Wv (hi-only, merged launch); Wq/Wk transpose hi+lo
    dim3 gS((unsigned)(nX / 1024), 2, 1);
    split_all<<<gS, thr256>>>(X, Wv, xh, wh + 2 * nW);
    dim3 gT(DIM / 32, DIM / 32, 2);
    tsplit_w<<<gT, thr256>>>(Wq, Wk, wh, wl);

    // fused: z=0 -> V^T proj (1-pass), z=1..4 -> M' split-K slices (2-pass)
    dim3 gF(DIM / 128, M / 128, 5);
    gemm_f16x<<<gF, thr128, SMEM_TOTAL>>>(
        nullptr, nullptr, nullptr, nullptr, nullptr, nullptr, nullptr,
        0, 0, 0, 0, 0, 0, 0, 0, 0, 6, 0);

    reduce4_hi<<<(unsigned)(nW / 1024), thr256>>>(mpart, mh);

    // T = X_hi @ M'_hi^T (1-pass, hi-only out)
    dim3 gTT(DIM / 128, M / 128, 1);
    gemm_f16x<<<gTT, thr128, SMEM_TOTAL>>>(xh, nullptr, mh, nullptr,
        nullptr, oh, nullptr, DIM, DIM, DIM, DIM,
        0, 0, 0, 0, 0, 1, 1);

    // scores -> pre-scaled f16 logits into ph (causal tile skip), 1-pass
    dim3 gScore(SEQ / 128, SEQ / 128, BATCH);
    gemm_f16x<<<gScore, thr128, SMEM_TOTAL>>>(oh, nullptr, xh, nullptr,
        nullptr, ph, nullptr, DIM, DIM, DIM, SEQ,
        (long)SEQ * DIM, (long)SEQ * DIM, (long)SEQ * SEQ, 1, 0, 5, 1);

    // softmax in place (vectorized, f16 logits -> f16 probs)
    softmax_causal<<<BATCH * SEQ, thr256>>>(ph);

    // out = P_hi @ V^T_hi per batch (k clamp, heavy-first), fp32 out; 1-pass
    dim3 gAV(DIM / 128, SEQ / 128, BATCH);
    gemm_f16x<<<gAV, thr128, SMEM_TOTAL>>>(ph, nullptr, oh + nX, nullptr,
        out, nullptr, nullptr, SEQ, SEQ, SEQ, DIM,
        (long)SEQ * SEQ, (long)DIM * SEQ, (long)SEQ * DIM, 0, 1, 0, 1);
}

// round 16
// speedup vs baseline: 1.0580x; 1.0580x over previous
#include <cuda_runtime.h>
#include <cuda_fp16.h>
#include <cstdint>

#define BATCH 4
#define SEQ   2048
#define DIM   1024

typedef __half f16;

static const long NX = (long)BATCH * SEQ * DIM;   // 8388608
static const long NW = (long)DIM * DIM;           // 1048576
#define DNX ((long)BATCH * SEQ * DIM)

// ---------------- scratch (device globals; allocation-free) ----------------
__device__ __align__(128) f16   g_xh[(long)BATCH*SEQ*DIM];
// [0]=Wq^T, [1]=Wk^T, [2]=Wv (hi only for Wv)
__device__ __align__(128) f16   g_wh[3][(long)DIM*DIM];
__device__ __align__(128) f16   g_wl[2][(long)DIM*DIM];
// M' split-K fp32 partials and final f16 hi
__device__ __align__(128) float g_mpart[4*(long)DIM*DIM];
__device__ __align__(128) f16   g_mh[(long)DIM*DIM];
// stacked outputs: [0]=T (hi), [1]=V^T (hi, [b][e][s])
__device__ __align__(128) f16   g_oh[2*(long)BATCH*SEQ*DIM];
// logits then probs (in-place softmax)
__device__ __align__(128) f16   g_ph[(long)BATCH*SEQ*SEQ];

// ---------------- PTX helpers (arch-generic; NO tcgen05) ----------------
__device__ __forceinline__ uint32_t smem_u32(const void* p) {
    uint32_t a;
    asm("{ .reg .u64 t; cvta.to.shared.u64 t, %1; cvt.u32.u64 %0, t; }" : "=r"(a) : "l"(p));
    return a;
}
__device__ __forceinline__ void cp16(uint32_t saddr, const void* g) {
    asm volatile("cp.async.cg.shared.global [%0], [%1], 16;" :: "r"(saddr), "l"(g) : "memory");
}
#define CP_COMMIT() asm volatile("cp.async.commit_group;" ::: "memory")

__device__ __forceinline__ void ldsm_x4(uint32_t* r, uint32_t addr) {
    asm volatile("ldmatrix.sync.aligned.m8n8.x4.shared.b16 {%0,%1,%2,%3}, [%4];"
        : "=r"(r[0]), "=r"(r[1]), "=r"(r[2]), "=r"(r[3]) : "r"(addr));
}
__device__ __forceinline__ void mma16816(float* c, const uint32_t* a, const uint32_t* b) {
    asm volatile("mma.sync.aligned.m16n8k16.row.col.f32.f16.f16.f32 "
        "{%0,%1,%2,%3}, {%4,%5,%6,%7}, {%8,%9}, {%0,%1,%2,%3};"
        : "+f"(c[0]), "+f"(c[1]), "+f"(c[2]), "+f"(c[3])
        : "r"(a[0]), "r"(a[1]), "r"(a[2]), "r"(a[3]), "r"(b[0]), "r"(b[1]));
}

__device__ __forceinline__ uint32_t swz(int row, int kc) {
    return (uint32_t)(row * 64 + ((kc ^ ((row >> 1) & 3)) << 4));
}

__device__ __forceinline__ void fsplit(float f, f16& h, f16& l) {
    h = __float2half_rn(f);
    l = __float2half_rn(f - __half2float(h));
}

// ---------------- SMEM layout ----------------
#define STAGES 3
#define STAGE_BYTES 32768
#define EPI_LD 132
#define SMEM_TOTAL (STAGES * STAGE_BYTES)

// =====================================================================
// fp16 hi/lo NT GEMM via mma.sync: 128x128 CTA tile, 128 threads,
// 4 warps x (64x64) warp tile.
// npass=3: hh + hl + lh ; npass=2: hh + lh ; npass=1: hh only
// mode 0: fp32 C
// mode 1: f16 C (hi; lo iff Clo != nullptr)
// mode 2: f16 C transposed (hi; lo iff Clo)
// mode 5: f16 C, scaled by 1/32, hi only  (scores -> logits)
// mode 6: fused (operands from device globals):
//         bz==0   -> V^T = X_hi @ Wv_hi^T (1-pass, mode-2 hi into g_oh+DNX)
//         bz=1..4 -> M' split-K slice bz-1 (2-pass, fp32 into g_mpart)
// =====================================================================
__global__ void __launch_bounds__(128, 2) gemm_f16x(
    const f16* __restrict__ Ahi, const f16* __restrict__ Alo,
    const f16* __restrict__ Bhi, const f16* __restrict__ Blo,
    float* __restrict__ Cf, f16* __restrict__ Chi, f16* __restrict__ Clo,
    int K, int ldA, int ldB, int ldC,
    long strideA, long strideB, long strideC,
    int causal, int kclamp, int mode, int npass)
{
    const int bx = blockIdx.x, bz = blockIdx.z;
    // heavy-tile-first dispatch when k-clamped
    const int by = kclamp ? ((int)gridDim.y - 1 - (int)blockIdx.y) : (int)blockIdx.y;
    if (causal && bx > by) return;

    // ---- resolve operands / submode ----
    const f16 *Ah = Ahi, *Al = Alo, *Bh = Bhi, *Bl = Blo;
    float* cf = Cf; f16 *chi = Chi, *clo = Clo;
    int emode = mode, ldc = ldC, np = npass, lda = ldA, ldb = ldB;
    long sA = strideA, sB = strideB, sC = strideC;
    int kk = K, kbase = 0, zi = bz;

    if (mode == 6) {
        if (bz == 0) {
            // V^T projection (1-pass, hi only)
            Ah = g_xh; Al = nullptr; Bh = g_wh[2]; Bl = nullptr;
            np = 1; emode = 2; ldc = SEQ; sC = (long)DIM * SEQ;
            chi = g_oh + DNX; clo = nullptr;
            lda = DIM; ldb = DIM; sA = 0; sB = 0; kk = DIM; zi = 0;
        } else {
            if (by >= DIM / 128) return;
            int zz = bz - 1;
            // M' slice: A = Wk^T (hi+lo), B = Wq^T (hi only) -> 2-pass
            Ah = g_wh[1]; Al = g_wl[1]; Bh = g_wh[0]; Bl = nullptr;
            np = 2; emode = 0; cf = g_mpart + (long)zz * NW;
            ldc = DIM; sC = 0; lda = DIM; ldb = DIM; sA = 0; sB = 0;
            kk = DIM / 4; kbase = zz * (DIM / 4); zi = 0;
        }
    }

    extern __shared__ char smem[];
    const uint32_t sbase = smem_u32(smem);
    const int tid  = threadIdx.x;        // 0..127
    const int lane = tid & 31;
    const int wid  = tid >> 5;           // 0..3
    const int wm   = wid >> 1;           // 0..1 : 64 rows
    const int wn   = wid & 1;            // 0..1 : 64 cols

    const int kmax    = kclamp ? min(kk, (by + 1) * 128) : kk;
    const int nchunks = kmax >> 5;       // BK = 32

    const f16* pAh = Ah + zi * sA + (long)by * 128 * lda;
    const f16* pAl = Al ? (Al + zi * sA + (long)by * 128 * lda) : nullptr;
    const f16* pBh = Bh + zi * sB + (long)bx * 128 * ldb;
    const f16* pBl = Bl ? (Bl + zi * sB + (long)bx * 128 * ldb) : nullptr;

    auto load_chunk = [&](int c) {
        const uint32_t st = sbase + (uint32_t)(c % STAGES) * STAGE_BYTES;
        const int k0 = kbase + (c << 5);
        #pragma unroll
        for (int i = 0; i < 4; i++) {
            int id  = tid + i * 128;       // 0..511
            int row = id >> 2, kc = id & 3;
            uint32_t so = swz(row, kc);
            long gA = (long)row * lda + k0 + kc * 8;
            long gB = (long)row * ldb + k0 + kc * 8;
            cp16(st +         so, pAh + gA);
            if (np >= 2) cp16(st +  8192 + so, pAl + gA);
            cp16(st + 16384 + so, pBh + gB);
            if (np == 3)  cp16(st + 24576 + so, pBl + gB);
        }
        CP_COMMIT();
    };

    float acc[4][8][4];
    #pragma unroll
    for (int i = 0; i < 4; i++)
        #pragma unroll
        for (int j = 0; j < 8; j++)
            #pragma unroll
            for (int p = 0; p < 4; p++) acc[i][j][p] = 0.f;

    load_chunk(0);
    if (nchunks > 1) load_chunk(1);

    const int lrow = lane & 15;
    const int lsel = lane >> 4;
    const int arow = wm * 64 + lrow;
    const int brow = wn * 64 + lrow;

    for (int c = 0; c < nchunks; c++) {
        if (c + 1 < nchunks) asm volatile("cp.async.wait_group 1;" ::: "memory");
        else                 asm volatile("cp.async.wait_group 0;" ::: "memory");
        __syncthreads();

        if (c + 2 < nchunks) load_chunk(c + 2);

        const uint32_t st  = sbase + (uint32_t)(c % STAGES) * STAGE_BYTES;
        const uint32_t sAh = st, sAl = st + 8192, sBh = st + 16384, sBl = st + 24576;

        #pragma unroll
        for (int ks = 0; ks < 2; ks++) {
            const int kc = ks * 2 + lsel;
            uint32_t bh[8][2];
            #pragma unroll
            for (int nq = 0; nq < 4; nq++) {
                int r = brow + nq * 16;
                uint32_t t4[4];
                ldsm_x4(t4, sBh + swz(r, kc));
                bh[nq*2][0] = t4[0]; bh[nq*2][1] = t4[2];
                bh[nq*2+1][0] = t4[1]; bh[nq*2+1][1] = t4[3];
            }
            uint32_t aH[4][4];
            #pragma unroll
            for (int mt = 0; mt < 4; mt++)
                ldsm_x4(aH[mt], sAh + swz(arow + mt * 16, kc));

            // pass 1: aH x bh
            #pragma unroll
            for (int mt = 0; mt < 4; mt++)
                #pragma unroll
                for (int nt = 0; nt < 8; nt++)
                    mma16816(acc[mt][nt], aH[mt], bh[nt]);

            // pass 2 (np==3): aH x bl
            if (np == 3) {
                uint32_t bl[8][2];
                #pragma unroll
                for (int nq = 0; nq < 4; nq++) {
                    int r = brow + nq * 16;
                    uint32_t t4[4];
                    ldsm_x4(t4, sBl + swz(r, kc));
                    bl[nq*2][0] = t4[0]; bl[nq*2][1] = t4[2];
                    bl[nq*2+1][0] = t4[1]; bl[nq*2+1][1] = t4[3];
                }
                #pragma unroll
                for (int mt = 0; mt < 4; mt++)
                    #pragma unroll
                    for (int nt = 0; nt < 8; nt++)
                        mma16816(acc[mt][nt], aH[mt], bl[nt]);
            }

            // pass 3 (np>=2): aL x bh (aL streamed)
            if (np >= 2) {
                uint32_t aL[2][4];
                ldsm_x4(aL[0], sAl + swz(arow, kc));
                #pragma unroll
                for (int mt = 0; mt < 4; mt++) {
                    const int cur = mt & 1;
                    if (mt < 3)
                        ldsm_x4(aL[cur ^ 1], sAl + swz(arow + (mt + 1) * 16, kc));
                    #pragma unroll
                    for (int nt = 0; nt < 8; nt++)
                        mma16816(acc[mt][nt], aL[cur], bh[nt]);
                }
            }
        }
    }

    // ---- epilogue: stage fp32 tile in smem, then coalesced global writes ----
    __syncthreads();
    float* buf = (float*)smem;
    {
        const int rq = lane >> 2;
        const int cq = (lane & 3) * 2;
        #pragma unroll
        for (int mt = 0; mt < 4; mt++)
            #pragma unroll
            for (int nt = 0; nt < 8; nt++) {
                int r0 = wm * 64 + mt * 16 + rq;
                int c0 = wn * 64 + nt * 8 + cq;
                *(float2*)&buf[r0 * EPI_LD + c0]       = make_float2(acc[mt][nt][0], acc[mt][nt][1]);
                *(float2*)&buf[(r0 + 8) * EPI_LD + c0] = make_float2(acc[mt][nt][2], acc[mt][nt][3]);
            }
    }
    __syncthreads();

    if (emode == 0) {
        int r = tid;
        long row = (long)by * 128 + r;
        float4* dst = (float4*)(cf + zi * sC + row * ldc + (long)bx * 128);
        #pragma unroll
        for (int i = 0; i < 32; i++)
            dst[i] = *(float4*)&buf[r * EPI_LD + i * 4];
    } else if (emode == 1) {
        int r = tid;
        long row = (long)by * 128 + r;
        f16* dh = chi + zi * sC + row * ldc + (long)bx * 128;
        f16* dl = clo ? (clo + zi * sC + row * ldc + (long)bx * 128) : nullptr;
        #pragma unroll
        for (int v = 0; v < 16; v++) {
            uint4 uh, ul;
            uint32_t* phh = (uint32_t*)&uh; uint32_t* pll = (uint32_t*)&ul;
            #pragma unroll
            for (int p = 0; p < 4; p++) {
                float f0 = buf[r * EPI_LD + v * 8 + p * 2];
                float f1 = buf[r * EPI_LD + v * 8 + p * 2 + 1];
                f16 h0, l0, h1, l1;
                fsplit(f0, h0, l0); fsplit(f1, h1, l1);
                phh[p] = (uint32_t)*(uint16_t*)&h0 | ((uint32_t)*(uint16_t*)&h1 << 16);
                pll[p] = (uint32_t)*(uint16_t*)&l0 | ((uint32_t)*(uint16_t*)&l1 << 16);
            }
            *(uint4*)(dh + v * 8) = uh;
            if (dl) *(uint4*)(dl + v * 8) = ul;
        }
    } else if (emode == 5) {
        // scaled f16 logits, hi only
        int r = tid;
        long row = (long)by * 128 + r;
        f16* dh = chi + zi * sC + row * ldc + (long)bx * 128;
        #pragma unroll
        for (int v = 0; v < 16; v++) {
            uint4 uh; uint32_t* phh = (uint32_t*)&uh;
            #pragma unroll
            for (int p = 0; p < 4; p++) {
                f16 h0 = __float2half_rn(buf[r * EPI_LD + v * 8 + p * 2]     * 0.03125f);
                f16 h1 = __float2half_rn(buf[r * EPI_LD + v * 8 + p * 2 + 1] * 0.03125f);
                phh[p] = (uint32_t)*(uint16_t*)&h0 | ((uint32_t)*(uint16_t*)&h1 << 16);
            }
            *(uint4*)(dh + v * 8) = uh;
        }
    } else {
        // emode 2: transposed out: Ct[e][s_local], batch derived from global row
        int cc = tid;
        int rowbase = by * 128;
        int b = rowbase / SEQ;
        int sloc = rowbase % SEQ;
        long e = (long)bx * 128 + cc;
        f16* dh = chi + b * sC + e * ldc + sloc;
        #pragma unroll
        for (int v = 0; v < 16; v++) {
            uint4 uh;
            uint32_t* phh = (uint32_t*)&uh;
            #pragma unroll
            for (int p = 0; p < 4; p++) {
                f16 h0 = __float2half_rn(buf[(v * 8 + p * 2)     * EPI_LD + cc]);
                f16 h1 = __float2half_rn(buf[(v * 8 + p * 2 + 1) * EPI_LD + cc]);
                phh[p] = (uint32_t)*(uint16_t*)&h0 | ((uint32_t)*(uint16_t*)&h1 << 16);
            }
            *(uint4*)(dh + v * 8) = uh;
        }
    }
}

// ---------------- fp32 -> f16 hi-only split (X and Wv in one launch) ----------------
__global__ void __launch_bounds__(256) split_all(
    const float* __restrict__ X, const float* __restrict__ Wv,
    f16* __restrict__ xh, f16* __restrict__ wvh)
{
    const float* src = (blockIdx.y == 0) ? X : Wv;
    f16* dst = (blockIdx.y == 0) ? xh : wvh;
    long n = (blockIdx.y == 0) ? NX : NW;
    long i = ((long)blockIdx.x * 256 + threadIdx.x) * 4;
    if (i >= n) return;
    float4 v = *(const float4*)(src + i);
    float f[4] = {v.x, v.y, v.z, v.w};
    uint32_t h2[2];
    #pragma unroll
    for (int p = 0; p < 2; p++) {
        f16 h0 = __float2half_rn(f[p*2]);
        f16 h1 = __float2half_rn(f[p*2+1]);
        h2[p] = (uint32_t)*(uint16_t*)&h0 | ((uint32_t)*(uint16_t*)&h1 << 16);
    }
    *(uint2*)(dst + i) = make_uint2(h2[0], h2[1]);
}

// transpose + split for Wq (z=0) and Wk (z=1): out[d][e] = in[e][d]
__global__ void __launch_bounds__(256) tsplit_w(
    const float* __restrict__ w0, const float* __restrict__ w1,
    f16* __restrict__ hi, f16* __restrict__ lo)
{
    const float* src = (blockIdx.z == 0) ? w0 : w1;
    f16* dh = hi + (long)blockIdx.z * NW;
    f16* dl = lo + (long)blockIdx.z * NW;

    __shared__ float t[32][33];
    const int tx = threadIdx.x & 31;
    const int ty = threadIdx.x >> 5;   // 0..7
    int x = blockIdx.x * 32 + tx;
    #pragma unroll
    for (int j = 0; j < 4; j++) {
        int y = blockIdx.y * 32 + ty + j * 8;
        t[ty + j * 8][tx] = src[(long)y * DIM + x];
    }
    __syncthreads();
    int xo = blockIdx.y * 32 + tx;
    #pragma unroll
    for (int j = 0; j < 4; j++) {
        int yo = blockIdx.x * 32 + ty + j * 8;
        float f = t[tx][ty + j * 8];
        f16 h, l;
        fsplit(f, h, l);
        dh[(long)yo * DIM + xo] = h;
        dl[(long)yo * DIM + xo] = l;
    }
}

// reduce 4 fp32 partials -> f16 hi only
__global__ void __launch_bounds__(256) reduce4_hi(
    const float* __restrict__ part, f16* __restrict__ hi)
{
    long i = ((long)blockIdx.x * 256 + threadIdx.x) * 4;
    if (i >= NW) return;
    float4 s = *(const float4*)(part + i);
    #pragma unroll
    for (int j = 1; j < 4; j++) {
        float4 v = *(const float4*)(part + j * NW + i);
        s.x += v.x; s.y += v.y; s.z += v.z; s.w += v.w;
    }
    float f[4] = {s.x, s.y, s.z, s.w};
    uint32_t h2[2];
    #pragma unroll
    for (int p = 0; p < 2; p++) {
        f16 h0 = __float2half_rn(f[p*2]);
        f16 h1 = __float2half_rn(f[p*2+1]);
        h2[p] = (uint32_t)*(uint16_t*)&h0 | ((uint32_t)*(uint16_t*)&h1 << 16);
    }
    *(uint2*)(hi + i) = make_uint2(h2[0], h2[1]);
}

// ---------------- causal softmax IN PLACE on f16 logits ----------------
// uint4 global access, float4 shared access (conflict-free), masked lanes
// -inf -> exp()=0. Zero-fill only to end of the row's 128-block.
__global__ void __launch_bounds__(256) softmax_causal(f16* __restrict__ P)
{
    const long r = blockIdx.x;
    const int  q = (int)(r & (SEQ - 1));
    f16* row = P + r * SEQ;

    __shared__ float bufr[SEQ];
    __shared__ float red[256];

    const int tid  = threadIdx.x;
    const int len  = q + 1;
    const int zend = ((q >> 7) + 1) << 7;     // round up to 128
    const int nvec = (len + 7) >> 3;          // 8-half vectors covering [0,len)

    float m = -1e30f;
    for (int v = tid; v < nvec; v += 256) {
        uint4 u = *(const uint4*)(row + v * 8);
        const f16* h = (const f16*)&u;
        float f[8];
        #pragma unroll
        for (int j = 0; j < 8; j++) {
            int idx = v * 8 + j;
            f[j] = (idx < len) ? __half2float(h[j]) : -1e30f;
            m = fmaxf(m, f[j]);
        }
        *(float4*)&bufr[v * 8]     = make_float4(f[0], f[1], f[2], f[3]);
        *(float4*)&bufr[v * 8 + 4] = make_float4(f[4], f[5], f[6], f[7]);
    }
    red[tid] = m;
    __syncthreads();
    #pragma unroll
    for (int s = 128; s > 0; s >>= 1) {
        if (tid < s) red[tid] = fmaxf(red[tid], red[tid + s]);
        __syncthreads();
    }
    m = red[0];
    __syncthreads();

    float sum = 0.f;
    for (int v = tid; v < nvec; v += 256) {
        float4 a = *(float4*)&bufr[v * 8];
        float4 b = *(float4*)&bufr[v * 8 + 4];
        float f[8] = {a.x, a.y, a.z, a.w, b.x, b.y, b.z, b.w};
        #pragma unroll
        for (int j = 0; j < 8; j++) {
            f[j] = __expf(f[j] - m);           // masked -> exp(-inf)=0
            sum += f[j];
        }
        *(float4*)&bufr[v * 8]     = make_float4(f[0], f[1], f[2], f[3]);
        *(float4*)&bufr[v * 8 + 4] = make_float4(f[4], f[5], f[6], f[7]);
    }
    red[tid] = sum;
    __syncthreads();
    #pragma unroll
    for (int s = 128; s > 0; s >>= 1) {
        if (tid < s) red[tid] += red[tid + s];
        __syncthreads();
    }
    const float inv = 1.0f / red[0];
    __syncthreads();

    const int zvec = zend >> 3;
    for (int v = tid; v < zvec; v += 256) {
        uint4 u; f16* h = (f16*)&u;
        if (v < nvec) {
            float4 a = *(float4*)&bufr[v * 8];
            float4 b = *(float4*)&bufr[v * 8 + 4];
            float f[8] = {a.x, a.y, a.z, a.w, b.x, b.y, b.z, b.w};
            #pragma unroll
            for (int j = 0; j < 8; j++) {
                int idx = v * 8 + j;
                h[j] = (idx < len) ? __float2half_rn(f[j] * inv) : __float2half(0.f);
            }
        } else {
            #pragma unroll
            for (int j = 0; j < 8; j++) h[j] = __float2half(0.f);
        }
        *(uint4*)(row + v * 8) = u;
    }
}

// ---------------------------------------------------------------------------
extern "C" void kernel_launch(void* const* d_in, const int* in_sizes, int n_in,
                              void* d_out, int out_size)
{
    const float* X  = (const float*)d_in[0];
    const float* Wq = (const float*)d_in[1];
    const float* Wk = (const float*)d_in[2];
    const float* Wv = (const float*)d_in[3];
    float* out = (float*)d_out;

    f16 *xh, *wh, *wl, *mh, *oh, *ph;
    float *mpart;
    cudaGetSymbolAddress((void**)&xh, g_xh);
    cudaGetSymbolAddress((void**)&wh, g_wh);  cudaGetSymbolAddress((void**)&wl, g_wl);
    cudaGetSymbolAddress((void**)&mh, g_mh);
    cudaGetSymbolAddress((void**)&mpart, g_mpart);
    cudaGetSymbolAddress((void**)&oh, g_oh);
    cudaGetSymbolAddress((void**)&ph, g_ph);

    cudaFuncSetAttribute(gemm_f16x, cudaFuncAttributeMaxDynamicSharedMemorySize, SMEM_TOTAL);

    const long nX = NX, nW = NW;
    const int M = BATCH * SEQ;  // 8192

    dim3 thr256(256);
    dim3 thr128(128);

    // splits: X + Wv (hi-only, merged launch); Wq/Wk transpose hi+lo
    dim3 gS((unsigned)(nX / 1024), 2, 1);
    split_all<<<gS, thr256>>>(X, Wv, xh, wh + 2 * nW);
    dim3 gT(DIM / 32, DIM / 32, 2);
    tsplit_w<<<gT, thr256>>>(Wq, Wk, wh, wl);

    // fused: z=0 -> V^T proj (1-pass), z=1..4 -> M' split-K slices (2-pass)
    dim3 gF(DIM / 128, M / 128, 5);
    gemm_f16x<<<gF, thr128, SMEM_TOTAL>>>(
        nullptr, nullptr, nullptr, nullptr, nullptr, nullptr, nullptr,
        0, 0, 0, 0, 0, 0, 0, 0, 0, 6, 0);

    reduce4_hi<<<(unsigned)(nW / 1024), thr256>>>(mpart, mh);

    // T = X_hi @ M'_hi^T (1-pass, hi-only out)
    dim3 gTT(DIM / 128, M / 128, 1);
    gemm_f16x<<<gTT, thr128, SMEM_TOTAL>>>(xh, nullptr, mh, nullptr,
        nullptr, oh, nullptr, DIM, DIM, DIM, DIM,
        0, 0, 0, 0, 0, 1, 1);

    // scores -> pre-scaled f16 logits into ph (causal tile skip), 1-pass
    dim3 gScore(SEQ / 128, SEQ / 128, BATCH);
    gemm_f16x<<<gScore, thr128, SMEM_TOTAL>>>(oh, nullptr, xh, nullptr,
        nullptr, ph, nullptr, DIM, DIM, DIM, SEQ,
        (long)SEQ * DIM, (long)SEQ * DIM, (long)SEQ * SEQ, 1, 0, 5, 1);

    // softmax in place (vectorized global + conflict-free smem)
    softmax_causal<<<BATCH * SEQ, thr256>>>(ph);

    // out = P_hi @ V^T_hi per batch (k clamp, heavy-first), fp32 out; 1-pass
    dim3 gAV(DIM / 128, SEQ / 128, BATCH);
    gemm_f16x<<<gAV, thr128, SMEM_TOTAL>>>(ph, nullptr, oh + nX, nullptr,
        out, nullptr, nullptr, SEQ, SEQ, SEQ, DIM,
        (long)SEQ * SEQ, (long)DIM * SEQ, (long)SEQ * DIM, 0, 1, 0, 1);
}

// round 17
// speedup vs baseline: 1.0820x; 1.0227x over previous
#include <cuda_runtime.h>
#include <cuda_fp16.h>
#include <cstdint>
#include <cmath>

#define BATCH 4
#define SEQ   2048
#define DIM   1024

typedef __half f16;

static const long NX = (long)BATCH * SEQ * DIM;   // 8388608
static const long NW = (long)DIM * DIM;           // 1048576
#define DNX ((long)BATCH * SEQ * DIM)

// ---------------- scratch (device globals; allocation-free) ----------------
__device__ __align__(128) f16   g_xh[(long)BATCH*SEQ*DIM];
// [0]=Wq^T, [1]=Wk^T, [2]=Wv  (all hi only)
__device__ __align__(128) f16   g_wh[3][(long)DIM*DIM];
// M' split-K fp32 partials and final f16 hi
__device__ __align__(128) float g_mpart[4*(long)DIM*DIM];
__device__ __align__(128) f16   g_mh[(long)DIM*DIM];
// stacked outputs: [0]=T (hi), [1]=V^T (hi, [b][e][s])
__device__ __align__(128) f16   g_oh[2*(long)BATCH*SEQ*DIM];
// logits then probs (in-place softmax)
__device__ __align__(128) f16   g_ph[(long)BATCH*SEQ*SEQ];

// ---------------- PTX helpers (arch-generic; NO tcgen05) ----------------
__device__ __forceinline__ uint32_t smem_u32(const void* p) {
    uint32_t a;
    asm("{ .reg .u64 t; cvta.to.shared.u64 t, %1; cvt.u32.u64 %0, t; }" : "=r"(a) : "l"(p));
    return a;
}
__device__ __forceinline__ void cp16(uint32_t saddr, const void* g) {
    asm volatile("cp.async.cg.shared.global [%0], [%1], 16;" :: "r"(saddr), "l"(g) : "memory");
}
#define CP_COMMIT() asm volatile("cp.async.commit_group;" ::: "memory")

__device__ __forceinline__ void ldsm_x4(uint32_t* r, uint32_t addr) {
    asm volatile("ldmatrix.sync.aligned.m8n8.x4.shared.b16 {%0,%1,%2,%3}, [%4];"
        : "=r"(r[0]), "=r"(r[1]), "=r"(r[2]), "=r"(r[3]) : "r"(addr));
}
__device__ __forceinline__ void mma16816(float* c, const uint32_t* a, const uint32_t* b) {
    asm volatile("mma.sync.aligned.m16n8k16.row.col.f32.f16.f16.f32 "
        "{%0,%1,%2,%3}, {%4,%5,%6,%7}, {%8,%9}, {%0,%1,%2,%3};"
        : "+f"(c[0]), "+f"(c[1]), "+f"(c[2]), "+f"(c[3])
        : "r"(a[0]), "r"(a[1]), "r"(a[2]), "r"(a[3]), "r"(b[0]), "r"(b[1]));
}

__device__ __forceinline__ uint32_t swz(int row, int kc) {
    return (uint32_t)(row * 64 + ((kc ^ ((row >> 1) & 3)) << 4));
}

// ---------------- SMEM layout ----------------
#define STAGES 3
#define STAGE_BYTES 32768
#define EPI_LD 132
#define SMEM_TOTAL (STAGES * STAGE_BYTES)

// =====================================================================
// fp16 NT GEMM via mma.sync: 128x128 CTA tile, 128 threads,
// 4 warps x (64x64) warp tile.
// npass=2: hh + lh (A_lo loaded); npass=1: hh only
// mode 0: fp32 C
// mode 1: f16 C hi
// mode 2: f16 C transposed hi
// mode 5: f16 C, scaled by 1/32, hi only  (scores -> logits)
// mode 6: fused (operands from device globals):
//         bz==0 -> V^T = X_hi @ Wv_hi^T (1-pass, mode-2 hi into g_oh+DNX)
//         bz==1 -> M' split-K slice (by>>3), local row (by&7); 1-pass fp32
// causal: 1 = skip bx>by (2D grid); 2 = packed lower-triangle 1D grid
// =====================================================================
__global__ void __launch_bounds__(128, 2) gemm_f16x(
    const f16* __restrict__ Ahi, const f16* __restrict__ Alo,
    const f16* __restrict__ Bhi,
    float* __restrict__ Cf, f16* __restrict__ Chi,
    int K, int ldA, int ldB, int ldC,
    long strideA, long strideB, long strideC,
    int causal, int kclamp, int mode, int npass)
{
    int bx = blockIdx.x;
    const int bz = blockIdx.z;
    int by;
    if (causal == 2) {
        // packed lower triangle: t -> (by, bx), by >= bx
        int t = blockIdx.x;
        int r = (int)((sqrtf(8.f * t + 1.f) - 1.f) * 0.5f);
        while ((r + 1) * (r + 2) / 2 <= t) r++;
        while (r * (r + 1) / 2 > t) r--;
        by = r; bx = t - r * (r + 1) / 2;
    } else {
        by = kclamp ? ((int)gridDim.y - 1 - (int)blockIdx.y) : (int)blockIdx.y;
        if (causal == 1 && bx > by) return;
    }

    // ---- resolve operands / submode ----
    const f16 *Ah = Ahi, *Al = Alo, *Bh = Bhi;
    float* cf = Cf; f16 *chi = Chi;
    int emode = mode, ldc = ldC, np = npass, lda = ldA, ldb = ldB;
    long sA = strideA, sB = strideB, sC = strideC;
    int kk = K, kbase = 0, zi = bz;

    if (mode == 6) {
        if (bz == 0) {
            // V^T projection (1-pass, hi only)
            Ah = g_xh; Al = nullptr; Bh = g_wh[2];
            np = 1; emode = 2; ldc = SEQ; sC = (long)DIM * SEQ;
            chi = g_oh + DNX;
            lda = DIM; ldb = DIM; sA = 0; sB = 0; kk = DIM; zi = 0;
        } else {
            if (by >= 32) return;          // 4 slices x 8 rows
            int zz = by >> 3;
            by = by & 7;
            Ah = g_wh[1]; Al = nullptr; Bh = g_wh[0];
            np = 1; emode = 0; cf = g_mpart + (long)zz * NW;
            ldc = DIM; sC = 0; lda = DIM; ldb = DIM; sA = 0; sB = 0;
            kk = DIM / 4; kbase = zz * (DIM / 4); zi = 0;
        }
    }

    extern __shared__ char smem[];
    const uint32_t sbase = smem_u32(smem);
    const int tid  = threadIdx.x;        // 0..127
    const int lane = tid & 31;
    const int wid  = tid >> 5;           // 0..3
    const int wm   = wid >> 1;           // 0..1 : 64 rows
    const int wn   = wid & 1;            // 0..1 : 64 cols

    const int kmax    = kclamp ? min(kk, (by + 1) * 128) : kk;
    const int nchunks = kmax >> 5;       // BK = 32

    const f16* pAh = Ah + zi * sA + (long)by * 128 * lda;
    const f16* pAl = Al ? (Al + zi * sA + (long)by * 128 * lda) : nullptr;
    const f16* pBh = Bh + zi * sB + (long)bx * 128 * ldb;

    auto load_chunk = [&](int c) {
        const uint32_t st = sbase + (uint32_t)(c % STAGES) * STAGE_BYTES;
        const int k0 = kbase + (c << 5);
        #pragma unroll
        for (int i = 0; i < 4; i++) {
            int id  = tid + i * 128;       // 0..511
            int row = id >> 2, kc = id & 3;
            uint32_t so = swz(row, kc);
            long gA = (long)row * lda + k0 + kc * 8;
            long gB = (long)row * ldb + k0 + kc * 8;
            cp16(st +         so, pAh + gA);
            if (np >= 2) cp16(st +  8192 + so, pAl + gA);
            cp16(st + 16384 + so, pBh + gB);
        }
        CP_COMMIT();
    };

    float acc[4][8][4];
    #pragma unroll
    for (int i = 0; i < 4; i++)
        #pragma unroll
        for (int j = 0; j < 8; j++)
            #pragma unroll
            for (int p = 0; p < 4; p++) acc[i][j][p] = 0.f;

    load_chunk(0);
    if (nchunks > 1) load_chunk(1);

    const int lrow = lane & 15;
    const int lsel = lane >> 4;
    const int arow = wm * 64 + lrow;
    const int brow = wn * 64 + lrow;

    for (int c = 0; c < nchunks; c++) {
        if (c + 1 < nchunks) asm volatile("cp.async.wait_group 1;" ::: "memory");
        else                 asm volatile("cp.async.wait_group 0;" ::: "memory");
        __syncthreads();

        if (c + 2 < nchunks) load_chunk(c + 2);

        const uint32_t st  = sbase + (uint32_t)(c % STAGES) * STAGE_BYTES;
        const uint32_t sAh = st, sAl = st + 8192, sBh = st + 16384;

        #pragma unroll
        for (int ks = 0; ks < 2; ks++) {
            const int kc = ks * 2 + lsel;
            uint32_t bh[8][2];
            #pragma unroll
            for (int nq = 0; nq < 4; nq++) {
                int r = brow + nq * 16;
                uint32_t t4[4];
                ldsm_x4(t4, sBh + swz(r, kc));
                bh[nq*2][0] = t4[0]; bh[nq*2][1] = t4[2];
                bh[nq*2+1][0] = t4[1]; bh[nq*2+1][1] = t4[3];
            }
            uint32_t aH[4][4];
            #pragma unroll
            for (int mt = 0; mt < 4; mt++)
                ldsm_x4(aH[mt], sAh + swz(arow + mt * 16, kc));

            // pass 1: aH x bh
            #pragma unroll
            for (int mt = 0; mt < 4; mt++)
                #pragma unroll
                for (int nt = 0; nt < 8; nt++)
                    mma16816(acc[mt][nt], aH[mt], bh[nt]);

            // pass 2 (np>=2): aL x bh (aL streamed)
            if (np >= 2) {
                uint32_t aL[2][4];
                ldsm_x4(aL[0], sAl + swz(arow, kc));
                #pragma unroll
                for (int mt = 0; mt < 4; mt++) {
                    const int cur = mt & 1;
                    if (mt < 3)
                        ldsm_x4(aL[cur ^ 1], sAl + swz(arow + (mt + 1) * 16, kc));
                    #pragma unroll
                    for (int nt = 0; nt < 8; nt++)
                        mma16816(acc[mt][nt], aL[cur], bh[nt]);
                }
            }
        }
    }

    // ---- epilogue: stage fp32 tile in smem, then coalesced global writes ----
    __syncthreads();
    float* buf = (float*)smem;
    {
        const int rq = lane >> 2;
        const int cq = (lane & 3) * 2;
        #pragma unroll
        for (int mt = 0; mt < 4; mt++)
            #pragma unroll
            for (int nt = 0; nt < 8; nt++) {
                int r0 = wm * 64 + mt * 16 + rq;
                int c0 = wn * 64 + nt * 8 + cq;
                *(float2*)&buf[r0 * EPI_LD + c0]       = make_float2(acc[mt][nt][0], acc[mt][nt][1]);
                *(float2*)&buf[(r0 + 8) * EPI_LD + c0] = make_float2(acc[mt][nt][2], acc[mt][nt][3]);
            }
    }
    __syncthreads();

    if (emode == 0) {
        int r = tid;
        long row = (long)by * 128 + r;
        float4* dst = (float4*)(cf + zi * sC + row * ldc + (long)bx * 128);
        #pragma unroll
        for (int i = 0; i < 32; i++)
            dst[i] = *(float4*)&buf[r * EPI_LD + i * 4];
    } else if (emode == 1) {
        int r = tid;
        long row = (long)by * 128 + r;
        f16* dh = chi + zi * sC + row * ldc + (long)bx * 128;
        #pragma unroll
        for (int v = 0; v < 16; v++) {
            uint4 uh; uint32_t* phh = (uint32_t*)&uh;
            #pragma unroll
            for (int p = 0; p < 4; p++) {
                f16 h0 = __float2half_rn(buf[r * EPI_LD + v * 8 + p * 2]);
                f16 h1 = __float2half_rn(buf[r * EPI_LD + v * 8 + p * 2 + 1]);
                phh[p] = (uint32_t)*(uint16_t*)&h0 | ((uint32_t)*(uint16_t*)&h1 << 16);
            }
            *(uint4*)(dh + v * 8) = uh;
        }
    } else if (emode == 5) {
        // scaled f16 logits, hi only
        int r = tid;
        long row = (long)by * 128 + r;
        f16* dh = chi + zi * sC + row * ldc + (long)bx * 128;
        #pragma unroll
        for (int v = 0; v < 16; v++) {
            uint4 uh; uint32_t* phh = (uint32_t*)&uh;
            #pragma unroll
            for (int p = 0; p < 4; p++) {
                f16 h0 = __float2half_rn(buf[r * EPI_LD + v * 8 + p * 2]     * 0.03125f);
                f16 h1 = __float2half_rn(buf[r * EPI_LD + v * 8 + p * 2 + 1] * 0.03125f);
                phh[p] = (uint32_t)*(uint16_t*)&h0 | ((uint32_t)*(uint16_t*)&h1 << 16);
            }
            *(uint4*)(dh + v * 8) = uh;
        }
    } else {
        // emode 2: transposed out: Ct[e][s_local], batch derived from global row
        int cc = tid;
        int rowbase = by * 128;
        int b = rowbase / SEQ;
        int sloc = rowbase % SEQ;
        long e = (long)bx * 128 + cc;
        f16* dh = chi + b * sC + e * ldc + sloc;
        #pragma unroll
        for (int v = 0; v < 16; v++) {
            uint4 uh;
            uint32_t* phh = (uint32_t*)&uh;
            #pragma unroll
            for (int p = 0; p < 4; p++) {
                f16 h0 = __float2half_rn(buf[(v * 8 + p * 2)     * EPI_LD + cc]);
                f16 h1 = __float2half_rn(buf[(v * 8 + p * 2 + 1) * EPI_LD + cc]);
                phh[p] = (uint32_t)*(uint16_t*)&h0 | ((uint32_t)*(uint16_t*)&h1 << 16);
            }
            *(uint4*)(dh + v * 8) = uh;
        }
    }
}

// ---------------- fp32 -> f16 hi-only split (X and Wv in one launch) ----------------
__global__ void __launch_bounds__(256) split_all(
    const float* __restrict__ X, const float* __restrict__ Wv,
    f16* __restrict__ xh, f16* __restrict__ wvh)
{
    const float* src = (blockIdx.y == 0) ? X : Wv;
    f16* dst = (blockIdx.y == 0) ? xh : wvh;
    long n = (blockIdx.y == 0) ? NX : NW;
    long i = ((long)blockIdx.x * 256 + threadIdx.x) * 4;
    if (i >= n) return;
    float4 v = *(const float4*)(src + i);
    float f[4] = {v.x, v.y, v.z, v.w};
    uint32_t h2[2];
    #pragma unroll
    for (int p = 0; p < 2; p++) {
        f16 h0 = __float2half_rn(f[p*2]);
        f16 h1 = __float2half_rn(f[p*2+1]);
        h2[p] = (uint32_t)*(uint16_t*)&h0 | ((uint32_t)*(uint16_t*)&h1 << 16);
    }
    *(uint2*)(dst + i) = make_uint2(h2[0], h2[1]);
}

// transpose hi-only for Wq (z=0) and Wk (z=1): out[d][e] = in[e][d]
__global__ void __launch_bounds__(256) tsplit_hi(
    const float* __restrict__ w0, const float* __restrict__ w1,
    f16* __restrict__ hi)
{
    const float* src = (blockIdx.z == 0) ? w0 : w1;
    f16* dh = hi + (long)blockIdx.z * NW;

    __shared__ float t[32][33];
    const int tx = threadIdx.x & 31;
    const int ty = threadIdx.x >> 5;   // 0..7
    int x = blockIdx.x * 32 + tx;
    #pragma unroll
    for (int j = 0; j < 4; j++) {
        int y = blockIdx.y * 32 + ty + j * 8;
        t[ty + j * 8][tx] = src[(long)y * DIM + x];
    }
    __syncthreads();
    int xo = blockIdx.y * 32 + tx;
    #pragma unroll
    for (int j = 0; j < 4; j++) {
        int yo = blockIdx.x * 32 + ty + j * 8;
        dh[(long)yo * DIM + xo] = __float2half_rn(t[tx][ty + j * 8]);
    }
}

// reduce 4 fp32 partials -> f16 hi only
__global__ void __launch_bounds__(256) reduce4_hi(
    const float* __restrict__ part, f16* __restrict__ hi)
{
    long i = ((long)blockIdx.x * 256 + threadIdx.x) * 4;
    if (i >= NW) return;
    float4 s = *(const float4*)(part + i);
    #pragma unroll
    for (int j = 1; j < 4; j++) {
        float4 v = *(const float4*)(part + j * NW + i);
        s.x += v.x; s.y += v.y; s.z += v.z; s.w += v.w;
    }
    float f[4] = {s.x, s.y, s.z, s.w};
    uint32_t h2[2];
    #pragma unroll
    for (int p = 0; p < 2; p++) {
        f16 h0 = __float2half_rn(f[p*2]);
        f16 h1 = __float2half_rn(f[p*2+1]);
        h2[p] = (uint32_t)*(uint16_t*)&h0 | ((uint32_t)*(uint16_t*)&h1 << 16);
    }
    *(uint2*)(hi + i) = make_uint2(h2[0], h2[1]);
}

// ---------------- causal softmax IN PLACE on f16 logits ----------------
// uint4 global access, float4 shared access (conflict-free), masked lanes
// -inf -> exp()=0. Zero-fill only to end of the row's 128-block.
__global__ void __launch_bounds__(256) softmax_causal(f16* __restrict__ P)
{
    const long r = blockIdx.x;
    const int  q = (int)(r & (SEQ - 1));
    f16* row = P + r * SEQ;

    __shared__ float bufr[SEQ];
    __shared__ float red[256];

    const int tid  = threadIdx.x;
    const int len  = q + 1;
    const int zend = ((q >> 7) + 1) << 7;     // round up to 128
    const int nvec = (len + 7) >> 3;          // 8-half vectors covering [0,len)

    float m = -1e30f;
    for (int v = tid; v < nvec; v += 256) {
        uint4 u = *(const uint4*)(row + v * 8);
        const f16* h = (const f16*)&u;
        float f[8];
        #pragma unroll
        for (int j = 0; j < 8; j++) {
            int idx = v * 8 + j;
            f[j] = (idx < len) ? __half2float(h[j]) : -1e30f;
            m = fmaxf(m, f[j]);
        }
        *(float4*)&bufr[v * 8]     = make_float4(f[0], f[1], f[2], f[3]);
        *(float4*)&bufr[v * 8 + 4] = make_float4(f[4], f[5], f[6], f[7]);
    }
    red[tid] = m;
    __syncthreads();
    #pragma unroll
    for (int s = 128; s > 0; s >>= 1) {
        if (tid < s) red[tid] = fmaxf(red[tid], red[tid + s]);
        __syncthreads();
    }
    m = red[0];
    __syncthreads();

    float sum = 0.f;
    for (int v = tid; v < nvec; v += 256) {
        float4 a = *(float4*)&bufr[v * 8];
        float4 b = *(float4*)&bufr[v * 8 + 4];
        float f[8] = {a.x, a.y, a.z, a.w, b.x, b.y, b.z, b.w};
        #pragma unroll
        for (int j = 0; j < 8; j++) {
            f[j] = __expf(f[j] - m);           // masked -> exp(-inf)=0
            sum += f[j];
        }
        *(float4*)&bufr[v * 8]     = make_float4(f[0], f[1], f[2], f[3]);
        *(float4*)&bufr[v * 8 + 4] = make_float4(f[4], f[5], f[6], f[7]);
    }
    red[tid] = sum;
    __syncthreads();
    #pragma unroll
    for (int s = 128; s > 0; s >>= 1) {
        if (tid < s) red[tid] += red[tid + s];
        __syncthreads();
    }
    const float inv = 1.0f / red[0];
    __syncthreads();

    const int zvec = zend >> 3;
    for (int v = tid; v < zvec; v += 256) {
        uint4 u; f16* h = (f16*)&u;
        if (v < nvec) {
            float4 a = *(float4*)&bufr[v * 8];
            float4 b = *(float4*)&bufr[v * 8 + 4];
            float f[8] = {a.x, a.y, a.z, a.w, b.x, b.y, b.z, b.w};
            #pragma unroll
            for (int j = 0; j < 8; j++) {
                int idx = v * 8 + j;
                h[j] = (idx < len) ? __float2half_rn(f[j] * inv) : __float2half(0.f);
            }
        } else {
            #pragma unroll
            for (int j = 0; j < 8; j++) h[j] = __float2half(0.f);
        }
        *(uint4*)(row + v * 8) = u;
    }
}

// ---------------------------------------------------------------------------
extern "C" void kernel_launch(void* const* d_in, const int* in_sizes, int n_in,
                              void* d_out, int out_size)
{
    const float* X  = (const float*)d_in[0];
    const float* Wq = (const float*)d_in[1];
    const float* Wk = (const float*)d_in[2];
    const float* Wv = (const float*)d_in[3];
    float* out = (float*)d_out;

    f16 *xh, *wh, *mh, *oh, *ph;
    float *mpart;
    cudaGetSymbolAddress((void**)&xh, g_xh);
    cudaGetSymbolAddress((void**)&wh, g_wh);
    cudaGetSymbolAddress((void**)&mh, g_mh);
    cudaGetSymbolAddress((void**)&mpart, g_mpart);
    cudaGetSymbolAddress((void**)&oh, g_oh);
    cudaGetSymbolAddress((void**)&ph, g_ph);

    cudaFuncSetAttribute(gemm_f16x, cudaFuncAttributeMaxDynamicSharedMemorySize, SMEM_TOTAL);

    const long nX = NX, nW = NW;
    const int M = BATCH * SEQ;  // 8192

    dim3 thr256(256);
    dim3 thr128(128);

    // splits: X + Wv (hi-only, merged launch); Wq/Wk transpose hi-only
    dim3 gS((unsigned)(nX / 1024), 2, 1);
    split_all<<<gS, thr256>>>(X, Wv, xh, wh + 2 * nW);
    dim3 gT(DIM / 32, DIM / 32, 2);
    tsplit_hi<<<gT, thr256>>>(Wq, Wk, wh);

    // fused: z=0 -> V^T proj (512 blocks), z=1 -> M' slices (by>>3, 256 active)
    dim3 gF(DIM / 128, M / 128, 2);
    gemm_f16x<<<gF, thr128, SMEM_TOTAL>>>(
        nullptr, nullptr, nullptr, nullptr, nullptr,
        0, 0, 0, 0, 0, 0, 0, 0, 0, 6, 0);

    reduce4_hi<<<(unsigned)(nW / 1024), thr256>>>(mpart, mh);

    // T = X_hi @ M'_hi^T (1-pass, hi-only out)
    dim3 gTT(DIM / 128, M / 128, 1);
    gemm_f16x<<<gTT, thr128, SMEM_TOTAL>>>(xh, nullptr, mh,
        nullptr, oh, DIM, DIM, DIM, DIM,
        0, 0, 0, 0, 0, 1, 1);

    // scores -> pre-scaled f16 logits (packed triangle grid), 1-pass
    dim3 gScore(136, 1, BATCH);   // 16*17/2 tiles per batch
    gemm_f16x<<<gScore, thr128, SMEM_TOTAL>>>(oh, nullptr, xh,
        nullptr, ph, DIM, DIM, DIM, SEQ,
        (long)SEQ * DIM, (long)SEQ * DIM, (long)SEQ * SEQ, 2, 0, 5, 1);

    // softmax in place (vectorized global + conflict-free smem)
    softmax_causal<<<BATCH * SEQ, thr256>>>(ph);

    // out = P_hi @ V^T_hi per batch (k clamp, heavy-first), fp32 out; 1-pass
    dim3 gAV(DIM / 128, SEQ / 128, BATCH);
    gemm_f16x<<<gAV, thr128, SMEM_TOTAL>>>(ph, nullptr, oh + nX,
        out, nullptr, SEQ, SEQ, SEQ, DIM,
        (long)SEQ * SEQ, (long)DIM * SEQ, (long)SEQ * DIM, 0, 1, 0, 1);
}